// round 10
// baseline (speedup 1.0000x reference)
#include <cuda_runtime.h>
#include <cstdint>
#include <math.h>

// Qwen3MoeSparseMoeBlock: B=2,S=1024 -> T=2048 tokens
#define T_TOK 2048
#define H_DIM 1024
#define I_DIM 512
#define N_EXP 16
#define TOPK  8
#define TROWS (T_TOK * TOPK)     // 16384 total routed rows (packed)

// ---------------- scratch (static device globals; total ~136 MB < known-good 192 MB) ----
__device__ int   g_counts[N_EXP];
__device__ int   g_off[N_EXP];                 // packed start row per expert
__device__ int   g_ep[TROWS];                  // (t,k) -> (e<<16)|pos
__device__ int   g_rows[TROWS];                // packed row -> token id
__device__ int   g_slot[TROWS];                // (t,k) -> packed row id
__device__ float g_combine[T_TOK * N_EXP];     // dense combine weights
__device__ float g_xt[T_TOK * H_DIM];          // tf32-rounded x (8 MB)
// g_hmid: [0, 8388608)  = packed hmid  [16384 x 512]   (32 MB)
//         [8388608, 2x) = w_down^T     [E,H,I] tf32    (32 MB)
__device__ float g_hmid[2 * 8388608];
// g_Y: prepass phase:  [0, 8388608) = w_gate^T [E,I,H]; [8388608, 2x) = w_up^T (64 MB)
//      output phase:   packed Y [16384 x 1024]          (64 MB, overwrites weights)
__device__ float g_Y[2 * 8388608];
#define HM_WD  8388608
#define Y_WU   8388608

// ---------------- PTX helpers ----------------
__device__ __forceinline__ uint32_t f2tf32(float f) {
    uint32_t r;
    asm volatile("cvt.rna.tf32.f32 %0, %1;\n" : "=r"(r) : "f"(f));
    return r;
}
__device__ __forceinline__ float tf32r(float f) { return __uint_as_float(f2tf32(f)); }

// mma.sync tf32: operands are raw 32-bit regs holding tf32-prerounded floats.
__device__ __forceinline__ void mma_tf32(float* d, const uint32_t* a, const uint32_t* b) {
    asm volatile(
        "mma.sync.aligned.m16n8k8.row.col.f32.tf32.tf32.f32 "
        "{%0,%1,%2,%3}, {%4,%5,%6,%7}, {%8,%9}, {%0,%1,%2,%3};\n"
        : "+f"(d[0]), "+f"(d[1]), "+f"(d[2]), "+f"(d[3])
        : "r"(a[0]), "r"(a[1]), "r"(a[2]), "r"(a[3]), "r"(b[0]), "r"(b[1]));
}

// ldmatrix x4 (b16): four 8x8 b16 tiles == four 8x4 tf32 tiles (exact tf32 frag layout)
__device__ __forceinline__ void ldsm4(uint32_t* r, uint32_t addr) {
    asm volatile("ldmatrix.sync.aligned.m8n8.x4.shared.b16 {%0,%1,%2,%3}, [%4];"
                 : "=r"(r[0]), "=r"(r[1]), "=r"(r[2]), "=r"(r[3]) : "r"(addr));
}

__device__ __forceinline__ void cp16(void* smem_dst, const void* gsrc) {
    uint32_t d = (uint32_t)__cvta_generic_to_shared(smem_dst);
    asm volatile("cp.async.cg.shared.global [%0], [%1], 16;\n" :: "r"(d), "l"(gsrc));
}
__device__ __forceinline__ void cp_commit() { asm volatile("cp.async.commit_group;\n"); }
template <int N>
__device__ __forceinline__ void cp_wait() { asm volatile("cp.async.wait_group %0;\n" :: "n"(N)); }

// ---------------- kernel 0: zero counters ----------------
__global__ void init_kernel() {
    if (threadIdx.x < N_EXP) g_counts[threadIdx.x] = 0;
}

// ---------------- kernel: x -> tf32-rounded copy ----------------
__global__ void __launch_bounds__(256) xcvt_kernel(const float* __restrict__ x) {
    int i = blockIdx.x * 256 + threadIdx.x;
    float4 v = ((const float4*)x)[i];
    v.x = tf32r(v.x); v.y = tf32r(v.y); v.z = tf32r(v.z); v.w = tf32r(v.w);
    ((float4*)g_xt)[i] = v;
}

// ---------------- kernel: per-expert weight transpose + tf32 round ----------------
// src [E, R, C] -> dst [E, C, R]; dst selected by mode (device globals, no host symbol addr)
__global__ void __launch_bounds__(256) transpose_kernel(
    const float* __restrict__ src, int R, int C, int mode)
{
    __shared__ float s[32][33];
    float* dstbase = (mode == 0) ? g_Y : (mode == 1) ? (g_Y + Y_WU) : (g_hmid + HM_WD);
    const int e = blockIdx.z;
    const float* S = src + (size_t)e * R * C;
    float* D = dstbase + (size_t)e * R * C;
    const int c0 = blockIdx.x * 32, r0 = blockIdx.y * 32;
    const int tx = threadIdx.x, ty = threadIdx.y;
#pragma unroll
    for (int j = 0; j < 4; j++)
        s[ty + j * 8][tx] = S[(size_t)(r0 + ty + j * 8) * C + c0 + tx];
    __syncthreads();
#pragma unroll
    for (int j = 0; j < 4; j++)
        D[(size_t)(c0 + ty + j * 8) * R + r0 + tx] = tf32r(s[tx][ty + j * 8]);
}

// ---------------- kernel 1: router (logits, top-8, per-expert counts) ----------------
__global__ void __launch_bounds__(256) router_kernel(
    const float* __restrict__ x, const float* __restrict__ gw,
    float* __restrict__ logits_out)
{
    const int warp = threadIdx.x >> 5, lane = threadIdx.x & 31;
    const int t = blockIdx.x * 8 + warp;
    const float* xr = x + (size_t)t * H_DIM;

    float acc[N_EXP];
#pragma unroll
    for (int e = 0; e < N_EXP; e++) acc[e] = 0.f;

    for (int i = 0; i < H_DIM / 32; i++) {
        int h = i * 32 + lane;
        float xv = xr[h];
        const float* g = gw + (size_t)h * N_EXP;
#pragma unroll
        for (int e = 0; e < N_EXP; e++) acc[e] = fmaf(xv, g[e], acc[e]);
    }
#pragma unroll
    for (int e = 0; e < N_EXP; e++) {
#pragma unroll
        for (int off = 16; off; off >>= 1)
            acc[e] += __shfl_xor_sync(0xFFFFFFFFu, acc[e], off);
    }

    if (lane == 0) {
        if (logits_out) {
#pragma unroll
            for (int e = 0; e < N_EXP; e++) logits_out[t * N_EXP + e] = acc[e];
        }
        float m = acc[0];
#pragma unroll
        for (int e = 1; e < N_EXP; e++) m = fmaxf(m, acc[e]);

        unsigned sel = 0;
        int   idx[TOPK];
        float w[TOPK];
        float ssum = 0.f;
#pragma unroll
        for (int k = 0; k < TOPK; k++) {
            float best = -3.0e38f; int bi = 0;
#pragma unroll
            for (int e = 0; e < N_EXP; e++) {
                if (!((sel >> e) & 1u) && acc[e] > best) { best = acc[e]; bi = e; }
            }
            sel |= (1u << bi);
            idx[k] = bi;
            w[k] = expf(acc[bi] - m);
            ssum += w[k];
        }
        float inv = 1.f / ssum;
        // compare-accumulate (no runtime-indexed local array)
#pragma unroll
        for (int e = 0; e < N_EXP; e++) {
            float ce = 0.f;
#pragma unroll
            for (int k = 0; k < TOPK; k++)
                ce += (idx[k] == e) ? w[k] * inv : 0.f;
            g_combine[t * N_EXP + e] = ce;
        }

#pragma unroll
        for (int k = 0; k < TOPK; k++) {
            int e = idx[k];
            int pos = atomicAdd(&g_counts[e], 1);
            g_ep[t * TOPK + k] = (e << 16) | pos;
        }
    }
}

// ---------------- kernel 1b: exclusive prefix offsets ----------------
__global__ void offsets_kernel() {
    if (threadIdx.x == 0) {
        int run = 0;
#pragma unroll
        for (int e = 0; e < N_EXP; e++) { g_off[e] = run; run += g_counts[e]; }
    }
}

// ---------------- kernel 1c: scatter packed row lists ----------------
__global__ void __launch_bounds__(256) scatter_kernel() {
    int i = blockIdx.x * 256 + threadIdx.x;   // i in [0, TROWS)
    int ep = g_ep[i];
    int row = g_off[ep >> 16] + (ep & 0xFFFF);
    g_rows[row] = i / TOPK;
    g_slot[i] = row;
}

// ---------------- GEMM tiling ----------------
// CTA tile 128x64, BK=16, 8 warps (4x2), warp tile 32x32.
// smem padded: row stride 20 floats (80B) -> conflict-free ldmatrix phases.
#define BM 128
#define BN 64
#define BK 16
#define STR 20               // floats per smem row
#define A_TB (BM * STR)      // floats per A buffer (2560)
#define B_TB (BN * STR)      // floats per B buffer (1280)

// ---------------- kernel 2: fused gate+up grouped GEMM + SiLU epilogue ----------------
// grid: (I/BN=8, 16, E=16), block 256. No min-blocks -> reg cap 255 -> no spill.
__global__ void __launch_bounds__(256) gu_kernel()
{
    const int e = blockIdx.z;
    const int n_e = g_counts[e];
    const int m0 = blockIdx.y * BM;
    if (m0 >= n_e) return;
    const int base = g_off[e];
    const int n0 = blockIdx.x * BN;

    __shared__ float As[2][A_TB];
    __shared__ float Bg[2][B_TB];
    __shared__ float Bu[2][B_TB];
    __shared__ int   rtok[BM];
    __shared__ float rw[BM];

    const int tid = threadIdx.x;
    if (tid < BM) {
        int r = m0 + tid;
        int tok = 0; float w = 0.f;
        if (r < n_e) { tok = g_rows[base + r]; w = g_combine[tok * N_EXP + e]; }
        rtok[tid] = tok; rw[tid] = w;
    }
    __syncthreads();

    const int warp = tid >> 5, lane = tid & 31;
    const int gid = lane >> 2, tig = lane & 3;
    const int wm = (warp >> 1) * 32, wn = (warp & 1) * 32;

    const uint32_t a_off = (uint32_t)((wm + (lane & 7) + ((lane >> 3) & 1) * 8) * STR * 4
                                      + ((lane >> 4) & 1) * 16);
    const uint32_t b_off = (uint32_t)((wn + (lane & 7) + ((lane >> 4) & 1) * 8) * STR * 4
                                      + ((lane >> 3) & 1) * 16);
    const uint32_t As_b = (uint32_t)__cvta_generic_to_shared(&As[0][0]);
    const uint32_t Bg_b = (uint32_t)__cvta_generic_to_shared(&Bg[0][0]);
    const uint32_t Bu_b = (uint32_t)__cvta_generic_to_shared(&Bu[0][0]);

    const float* wgT = g_Y + (size_t)e * I_DIM * H_DIM;           // [I, H] n-major
    const float* wuT = g_Y + Y_WU + (size_t)e * I_DIM * H_DIM;

    float dG[2][4][4] = {}, dU[2][4][4] = {};

    auto load_stage = [&](int kt, int buf) {
        const int k0 = kt * BK;
#pragma unroll
        for (int j = 0; j < 2; j++) {
            int idx = tid + 256 * j;              // 512 chunks = 128 rows x 4
            int row = idx >> 2, c4 = idx & 3;
            cp16(&As[buf][row * STR + c4 * 4],
                 g_xt + (size_t)rtok[row] * H_DIM + k0 + c4 * 4);
        }
        {
            int row = tid >> 2, c4 = tid & 3;     // 256 chunks = 64 rows x 4
            cp16(&Bg[buf][row * STR + c4 * 4],
                 wgT + (size_t)(n0 + row) * H_DIM + k0 + c4 * 4);
            cp16(&Bu[buf][row * STR + c4 * 4],
                 wuT + (size_t)(n0 + row) * H_DIM + k0 + c4 * 4);
        }
        cp_commit();
    };

    const int KT = H_DIM / BK;  // 64
    load_stage(0, 0);

    for (int kt = 0; kt < KT; kt++) {
        int buf = kt & 1;
        if (kt + 1 < KT) { load_stage(kt + 1, buf ^ 1); cp_wait<1>(); }
        else             { cp_wait<0>(); }
        __syncthreads();

        const uint32_t As_t = As_b + (uint32_t)buf * (A_TB * 4);
        const uint32_t Bg_t = Bg_b + (uint32_t)buf * (B_TB * 4);
        const uint32_t Bu_t = Bu_b + (uint32_t)buf * (B_TB * 4);

#pragma unroll
        for (int ks = 0; ks < 2; ks++) {
            uint32_t a[2][4];
            ldsm4(a[0], As_t + a_off + ks * 32);
            ldsm4(a[1], As_t + a_off + 1280 + ks * 32);   // +16 rows * 80B
            uint32_t f0[4], f1[4];
            ldsm4(f0, Bg_t + b_off + ks * 32);
            ldsm4(f1, Bg_t + b_off + 1280 + ks * 32);
#pragma unroll
            for (int mi = 0; mi < 2; mi++) {
                mma_tf32(dG[mi][0], a[mi], &f0[0]);
                mma_tf32(dG[mi][1], a[mi], &f0[2]);
                mma_tf32(dG[mi][2], a[mi], &f1[0]);
                mma_tf32(dG[mi][3], a[mi], &f1[2]);
            }
            ldsm4(f0, Bu_t + b_off + ks * 32);
            ldsm4(f1, Bu_t + b_off + 1280 + ks * 32);
#pragma unroll
            for (int mi = 0; mi < 2; mi++) {
                mma_tf32(dU[mi][0], a[mi], &f0[0]);
                mma_tf32(dU[mi][1], a[mi], &f0[2]);
                mma_tf32(dU[mi][2], a[mi], &f1[0]);
                mma_tf32(dU[mi][3], a[mi], &f1[2]);
            }
        }
        __syncthreads();
    }

    // epilogue: hmid = tf32_round( silu(G) * U * combine_weight ), packed rows
#pragma unroll
    for (int mi = 0; mi < 2; mi++) {
#pragma unroll
        for (int ni = 0; ni < 4; ni++) {
            int rr = wm + mi * 16 + gid;
            int cc = wn + ni * 8 + tig * 2;
#pragma unroll
            for (int q = 0; q < 4; q++) {
                int r = rr + (q >> 1) * 8;
                int c = cc + (q & 1);
                if (m0 + r < n_e) {
                    float g = dG[mi][ni][q], u = dU[mi][ni][q];
                    float s = g / (1.f + expf(-g));
                    g_hmid[(size_t)(base + m0 + r) * I_DIM + n0 + c] =
                        tf32r(s * u * rw[r]);
                }
            }
        }
    }
}

// ---------------- kernel 3: down grouped GEMM ----------------
// grid: (H/BN=16, 16, E=16), block 256
__global__ void __launch_bounds__(256) down_kernel()
{
    const int e = blockIdx.z;
    const int n_e = g_counts[e];
    const int m0 = blockIdx.y * BM;
    if (m0 >= n_e) return;
    const int base = g_off[e];
    const int n0 = blockIdx.x * BN;

    __shared__ float As[2][A_TB];
    __shared__ float Bs[2][B_TB];

    const int tid = threadIdx.x;
    const int warp = tid >> 5, lane = tid & 31;
    const int gid = lane >> 2, tig = lane & 3;
    const int wm = (warp >> 1) * 32, wn = (warp & 1) * 32;

    const uint32_t a_off = (uint32_t)((wm + (lane & 7) + ((lane >> 3) & 1) * 8) * STR * 4
                                      + ((lane >> 4) & 1) * 16);
    const uint32_t b_off = (uint32_t)((wn + (lane & 7) + ((lane >> 4) & 1) * 8) * STR * 4
                                      + ((lane >> 3) & 1) * 16);
    const uint32_t As_b = (uint32_t)__cvta_generic_to_shared(&As[0][0]);
    const uint32_t Bs_b = (uint32_t)__cvta_generic_to_shared(&Bs[0][0]);

    const float* Ain = g_hmid + (size_t)base * I_DIM;                   // packed rows
    const float* wdT = g_hmid + HM_WD + (size_t)e * H_DIM * I_DIM;      // [H, I] n-major

    float dD[2][4][4] = {};

    auto load_stage = [&](int kt, int buf) {
        const int k0 = kt * BK;
#pragma unroll
        for (int j = 0; j < 2; j++) {
            int idx = tid + 256 * j;
            int row = idx >> 2, c4 = idx & 3;
            cp16(&As[buf][row * STR + c4 * 4],
                 Ain + (size_t)(m0 + row) * I_DIM + k0 + c4 * 4);
        }
        {
            int row = tid >> 2, c4 = tid & 3;
            cp16(&Bs[buf][row * STR + c4 * 4],
                 wdT + (size_t)(n0 + row) * I_DIM + k0 + c4 * 4);
        }
        cp_commit();
    };

    const int KT = I_DIM / BK;  // 32
    load_stage(0, 0);

    for (int kt = 0; kt < KT; kt++) {
        int buf = kt & 1;
        if (kt + 1 < KT) { load_stage(kt + 1, buf ^ 1); cp_wait<1>(); }
        else             { cp_wait<0>(); }
        __syncthreads();

        const uint32_t As_t = As_b + (uint32_t)buf * (A_TB * 4);
        const uint32_t Bs_t = Bs_b + (uint32_t)buf * (B_TB * 4);

#pragma unroll
        for (int ks = 0; ks < 2; ks++) {
            uint32_t a[2][4];
            ldsm4(a[0], As_t + a_off + ks * 32);
            ldsm4(a[1], As_t + a_off + 1280 + ks * 32);
            uint32_t f0[4], f1[4];
            ldsm4(f0, Bs_t + b_off + ks * 32);
            ldsm4(f1, Bs_t + b_off + 1280 + ks * 32);
#pragma unroll
            for (int mi = 0; mi < 2; mi++) {
                mma_tf32(dD[mi][0], a[mi], &f0[0]);
                mma_tf32(dD[mi][1], a[mi], &f0[2]);
                mma_tf32(dD[mi][2], a[mi], &f1[0]);
                mma_tf32(dD[mi][3], a[mi], &f1[2]);
            }
        }
        __syncthreads();
    }

#pragma unroll
    for (int mi = 0; mi < 2; mi++) {
#pragma unroll
        for (int ni = 0; ni < 4; ni++) {
            int rr = wm + mi * 16 + gid;
            int cc = wn + ni * 8 + tig * 2;
#pragma unroll
            for (int q = 0; q < 4; q++) {
                int r = rr + (q >> 1) * 8;
                int c = cc + (q & 1);
                if (m0 + r < n_e)
                    g_Y[(size_t)(base + m0 + r) * H_DIM + n0 + c] = dD[mi][ni][q];
            }
        }
    }
}

// ---------------- kernel 4: per-token combine ----------------
__global__ void __launch_bounds__(256) combine_kernel(float* __restrict__ out)
{
    const int t = blockIdx.x;
    __shared__ int slots[TOPK];
    if (threadIdx.x < TOPK) slots[threadIdx.x] = g_slot[t * TOPK + threadIdx.x];
    __syncthreads();

    int h4 = threadIdx.x;  // 256 float4 per token (H=1024)
    float4 acc = make_float4(0.f, 0.f, 0.f, 0.f);
#pragma unroll
    for (int k = 0; k < TOPK; k++) {
        const float4* y = (const float4*)(g_Y + (size_t)slots[k] * H_DIM);
        float4 v = y[h4];
        acc.x += v.x; acc.y += v.y; acc.z += v.z; acc.w += v.w;
    }
    ((float4*)out)[(size_t)t * (H_DIM / 4) + h4] = acc;
}

// ---------------- launch ----------------
extern "C" void kernel_launch(void* const* d_in, const int* in_sizes, int n_in,
                              void* d_out, int out_size)
{
    const float* x      = (const float*)d_in[0];  // [2,1024,1024]
    const float* gate_w = (const float*)d_in[1];  // [1024,16]
    const float* w_gate = (const float*)d_in[2];  // [16,1024,512]
    const float* w_up   = (const float*)d_in[3];  // [16,1024,512]
    const float* w_down = (const float*)d_in[4];  // [16,512,1024]
    float* out = (float*)d_out;

    float* logits = nullptr;
    if (out_size >= T_TOK * H_DIM + T_TOK * N_EXP)
        logits = out + (size_t)T_TOK * H_DIM;

    init_kernel<<<1, 32>>>();
    xcvt_kernel<<<(T_TOK * H_DIM / 4) / 256, 256>>>(x);
    transpose_kernel<<<dim3(I_DIM / 32, H_DIM / 32, N_EXP), dim3(32, 8)>>>(w_gate, H_DIM, I_DIM, 0);
    transpose_kernel<<<dim3(I_DIM / 32, H_DIM / 32, N_EXP), dim3(32, 8)>>>(w_up,   H_DIM, I_DIM, 1);
    transpose_kernel<<<dim3(H_DIM / 32, I_DIM / 32, N_EXP), dim3(32, 8)>>>(w_down, I_DIM, H_DIM, 2);
    router_kernel<<<T_TOK / 8, 256>>>(x, gate_w, logits);
    offsets_kernel<<<1, 32>>>();
    scatter_kernel<<<TROWS / 256, 256>>>();
    gu_kernel<<<dim3(I_DIM / BN, 16, N_EXP), 256>>>();
    down_kernel<<<dim3(H_DIM / BN, 16, N_EXP), 256>>>();
    combine_kernel<<<T_TOK, 256>>>(out);
}

// round 11
// speedup vs baseline: 1.1667x; 1.1667x over previous
#include <cuda_runtime.h>
#include <cstdint>
#include <math.h>

// Qwen3MoeSparseMoeBlock: B=2,S=1024 -> T=2048 tokens
#define T_TOK 2048
#define H_DIM 1024
#define I_DIM 512
#define N_EXP 16
#define TOPK  8
#define TROWS (T_TOK * TOPK)     // 16384 total routed rows (packed)

// ---------------- scratch (static device globals; total ~136 MB, known-good) ----------
__device__ int   g_counts[N_EXP];
__device__ int   g_off[N_EXP];                 // packed start row per expert
__device__ int   g_ep[TROWS];                  // (t,k) -> (e<<16)|pos
__device__ int   g_rows[TROWS];                // packed row -> token id
__device__ int   g_slot[TROWS];                // (t,k) -> packed row id
__device__ float g_combine[T_TOK * N_EXP];     // dense combine weights
__device__ float g_xt[T_TOK * H_DIM];          // tf32-rounded x (8 MB)
// g_hmid: [0, 8388608)  = packed hmid  [16384 x 512]   (32 MB)
//         [8388608, 2x) = w_down^T     [E,H,I] tf32    (32 MB)
__device__ float g_hmid[2 * 8388608];
// g_Y: prepass phase:  [0, 8388608) = w_gate^T [E,I,H]; [8388608, 2x) = w_up^T (64 MB)
//      output phase:   packed Y [16384 x 1024]          (64 MB, overwrites weights)
__device__ float g_Y[2 * 8388608];
#define HM_WD  8388608
#define Y_WU   8388608

// ---------------- PTX helpers ----------------
__device__ __forceinline__ uint32_t f2tf32(float f) {
    uint32_t r;
    asm volatile("cvt.rna.tf32.f32 %0, %1;\n" : "=r"(r) : "f"(f));
    return r;
}
__device__ __forceinline__ float tf32r(float f) { return __uint_as_float(f2tf32(f)); }

// mma.sync tf32: operands are raw 32-bit regs holding tf32-prerounded floats.
__device__ __forceinline__ void mma_tf32(float* d, const uint32_t* a, const uint32_t* b) {
    asm volatile(
        "mma.sync.aligned.m16n8k8.row.col.f32.tf32.tf32.f32 "
        "{%0,%1,%2,%3}, {%4,%5,%6,%7}, {%8,%9}, {%0,%1,%2,%3};\n"
        : "+f"(d[0]), "+f"(d[1]), "+f"(d[2]), "+f"(d[3])
        : "r"(a[0]), "r"(a[1]), "r"(a[2]), "r"(a[3]), "r"(b[0]), "r"(b[1]));
}

// ldmatrix x4 (b16): four 8x8 b16 tiles == four 8x4 tf32 tiles (exact tf32 frag layout)
__device__ __forceinline__ void ldsm4(uint32_t* r, uint32_t addr) {
    asm volatile("ldmatrix.sync.aligned.m8n8.x4.shared.b16 {%0,%1,%2,%3}, [%4];"
                 : "=r"(r[0]), "=r"(r[1]), "=r"(r[2]), "=r"(r[3]) : "r"(addr));
}

__device__ __forceinline__ void cp16(void* smem_dst, const void* gsrc) {
    uint32_t d = (uint32_t)__cvta_generic_to_shared(smem_dst);
    asm volatile("cp.async.cg.shared.global [%0], [%1], 16;\n" :: "r"(d), "l"(gsrc));
}
__device__ __forceinline__ void cp_commit() { asm volatile("cp.async.commit_group;\n"); }
template <int N>
__device__ __forceinline__ void cp_wait() { asm volatile("cp.async.wait_group %0;\n" :: "n"(N)); }

// ---------------- kernel 0: zero counters ----------------
__global__ void init_kernel() {
    if (threadIdx.x < N_EXP) g_counts[threadIdx.x] = 0;
}

// ---------------- kernel: x -> tf32-rounded copy ----------------
__global__ void __launch_bounds__(256) xcvt_kernel(const float* __restrict__ x) {
    int i = blockIdx.x * 256 + threadIdx.x;
    float4 v = ((const float4*)x)[i];
    v.x = tf32r(v.x); v.y = tf32r(v.y); v.z = tf32r(v.z); v.w = tf32r(v.w);
    ((float4*)g_xt)[i] = v;
}

// ---------------- kernel: per-expert weight transpose + tf32 round ----------------
// src [E, R, C] -> dst [E, C, R]; dst selected by mode
__global__ void __launch_bounds__(256) transpose_kernel(
    const float* __restrict__ src, int R, int C, int mode)
{
    __shared__ float s[32][33];
    float* dstbase = (mode == 0) ? g_Y : (mode == 1) ? (g_Y + Y_WU) : (g_hmid + HM_WD);
    const int e = blockIdx.z;
    const float* S = src + (size_t)e * R * C;
    float* D = dstbase + (size_t)e * R * C;
    const int c0 = blockIdx.x * 32, r0 = blockIdx.y * 32;
    const int tx = threadIdx.x, ty = threadIdx.y;
#pragma unroll
    for (int j = 0; j < 4; j++)
        s[ty + j * 8][tx] = S[(size_t)(r0 + ty + j * 8) * C + c0 + tx];
    __syncthreads();
#pragma unroll
    for (int j = 0; j < 4; j++)
        D[(size_t)(c0 + ty + j * 8) * R + r0 + tx] = tf32r(s[tx][ty + j * 8]);
}

// ---------------- kernel 1: router (logits, top-8, per-expert counts) ----------------
__global__ void __launch_bounds__(256) router_kernel(
    const float* __restrict__ x, const float* __restrict__ gw,
    float* __restrict__ logits_out)
{
    const int warp = threadIdx.x >> 5, lane = threadIdx.x & 31;
    const int t = blockIdx.x * 8 + warp;
    const float* xr = x + (size_t)t * H_DIM;

    float acc[N_EXP];
#pragma unroll
    for (int e = 0; e < N_EXP; e++) acc[e] = 0.f;

    for (int i = 0; i < H_DIM / 32; i++) {
        int h = i * 32 + lane;
        float xv = xr[h];
        const float* g = gw + (size_t)h * N_EXP;
#pragma unroll
        for (int e = 0; e < N_EXP; e++) acc[e] = fmaf(xv, g[e], acc[e]);
    }
#pragma unroll
    for (int e = 0; e < N_EXP; e++) {
#pragma unroll
        for (int off = 16; off; off >>= 1)
            acc[e] += __shfl_xor_sync(0xFFFFFFFFu, acc[e], off);
    }

    if (lane == 0) {
        if (logits_out) {
#pragma unroll
            for (int e = 0; e < N_EXP; e++) logits_out[t * N_EXP + e] = acc[e];
        }
        float m = acc[0];
#pragma unroll
        for (int e = 1; e < N_EXP; e++) m = fmaxf(m, acc[e]);

        unsigned sel = 0;
        int   idx[TOPK];
        float w[TOPK];
        float ssum = 0.f;
#pragma unroll
        for (int k = 0; k < TOPK; k++) {
            float best = -3.0e38f; int bi = 0;
#pragma unroll
            for (int e = 0; e < N_EXP; e++) {
                if (!((sel >> e) & 1u) && acc[e] > best) { best = acc[e]; bi = e; }
            }
            sel |= (1u << bi);
            idx[k] = bi;
            w[k] = expf(acc[bi] - m);
            ssum += w[k];
        }
        float inv = 1.f / ssum;
        // compare-accumulate (no runtime-indexed local array)
#pragma unroll
        for (int e = 0; e < N_EXP; e++) {
            float ce = 0.f;
#pragma unroll
            for (int k = 0; k < TOPK; k++)
                ce += (idx[k] == e) ? w[k] * inv : 0.f;
            g_combine[t * N_EXP + e] = ce;
        }

#pragma unroll
        for (int k = 0; k < TOPK; k++) {
            int e = idx[k];
            int pos = atomicAdd(&g_counts[e], 1);
            g_ep[t * TOPK + k] = (e << 16) | pos;
        }
    }
}

// ---------------- kernel 1b: exclusive prefix offsets ----------------
__global__ void offsets_kernel() {
    if (threadIdx.x == 0) {
        int run = 0;
#pragma unroll
        for (int e = 0; e < N_EXP; e++) { g_off[e] = run; run += g_counts[e]; }
    }
}

// ---------------- kernel 1c: scatter packed row lists ----------------
__global__ void __launch_bounds__(256) scatter_kernel() {
    int i = blockIdx.x * 256 + threadIdx.x;   // i in [0, TROWS)
    int ep = g_ep[i];
    int row = g_off[ep >> 16] + (ep & 0xFFFF);
    g_rows[row] = i / TOPK;
    g_slot[i] = row;
}

// ---------------- GEMM tiling ----------------
// CTA tile 128x64, BK=16, 8 warps (4x2), warp tile 32x32.
// smem padded: row stride 20 floats (80B) -> conflict-free ldmatrix phases.
#define BM 128
#define BN 64
#define BK 16
#define STR 20               // floats per smem row
#define A_TB (BM * STR)      // floats per A buffer (2560)
#define B_TB (BN * STR)      // floats per B buffer (1280)

// ---------------- kernel 2: fused gate+up grouped GEMM + SiLU epilogue ----------------
// grid: (I/BN=8, 16, E=16), block 256. min-blocks=2 -> reg cap 128 -> 2 CTAs/SM.
__global__ void __launch_bounds__(256, 2) gu_kernel()
{
    const int e = blockIdx.z;
    const int n_e = g_counts[e];
    const int m0 = blockIdx.y * BM;
    if (m0 >= n_e) return;
    const int base = g_off[e];
    const int n0 = blockIdx.x * BN;

    __shared__ float As[2][A_TB];
    __shared__ float Bg[2][B_TB];
    __shared__ float Bu[2][B_TB];
    __shared__ int   rtok[BM];
    __shared__ float rw[BM];

    const int tid = threadIdx.x;
    if (tid < BM) {
        int r = m0 + tid;
        int tok = 0; float w = 0.f;
        if (r < n_e) { tok = g_rows[base + r]; w = g_combine[tok * N_EXP + e]; }
        rtok[tid] = tok; rw[tid] = w;
    }
    __syncthreads();

    const int warp = tid >> 5, lane = tid & 31;
    const int gid = lane >> 2, tig = lane & 3;
    const int wm = (warp >> 1) * 32, wn = (warp & 1) * 32;

    const uint32_t a_off = (uint32_t)((wm + (lane & 7) + ((lane >> 3) & 1) * 8) * STR * 4
                                      + ((lane >> 4) & 1) * 16);
    const uint32_t b_off = (uint32_t)((wn + (lane & 7) + ((lane >> 4) & 1) * 8) * STR * 4
                                      + ((lane >> 3) & 1) * 16);
    const uint32_t As_b = (uint32_t)__cvta_generic_to_shared(&As[0][0]);
    const uint32_t Bg_b = (uint32_t)__cvta_generic_to_shared(&Bg[0][0]);
    const uint32_t Bu_b = (uint32_t)__cvta_generic_to_shared(&Bu[0][0]);

    const float* wgT = g_Y + (size_t)e * I_DIM * H_DIM;           // [I, H] n-major
    const float* wuT = g_Y + Y_WU + (size_t)e * I_DIM * H_DIM;

    float dG[2][4][4] = {}, dU[2][4][4] = {};

    auto load_stage = [&](int kt, int buf) {
        const int k0 = kt * BK;
#pragma unroll
        for (int j = 0; j < 2; j++) {
            int idx = tid + 256 * j;              // 512 chunks = 128 rows x 4
            int row = idx >> 2, c4 = idx & 3;
            cp16(&As[buf][row * STR + c4 * 4],
                 g_xt + (size_t)rtok[row] * H_DIM + k0 + c4 * 4);
        }
        {
            int row = tid >> 2, c4 = tid & 3;     // 256 chunks = 64 rows x 4
            cp16(&Bg[buf][row * STR + c4 * 4],
                 wgT + (size_t)(n0 + row) * H_DIM + k0 + c4 * 4);
            cp16(&Bu[buf][row * STR + c4 * 4],
                 wuT + (size_t)(n0 + row) * H_DIM + k0 + c4 * 4);
        }
        cp_commit();
    };

    const int KT = H_DIM / BK;  // 64
    load_stage(0, 0);

    for (int kt = 0; kt < KT; kt++) {
        int buf = kt & 1;
        if (kt + 1 < KT) { load_stage(kt + 1, buf ^ 1); cp_wait<1>(); }
        else             { cp_wait<0>(); }
        __syncthreads();

        const uint32_t As_t = As_b + (uint32_t)buf * (A_TB * 4);
        const uint32_t Bg_t = Bg_b + (uint32_t)buf * (B_TB * 4);
        const uint32_t Bu_t = Bu_b + (uint32_t)buf * (B_TB * 4);

#pragma unroll
        for (int ks = 0; ks < 2; ks++) {
            uint32_t a[2][4];
            ldsm4(a[0], As_t + a_off + ks * 32);
            ldsm4(a[1], As_t + a_off + 1280 + ks * 32);   // +16 rows * 80B
            uint32_t f0[4], f1[4];
            ldsm4(f0, Bg_t + b_off + ks * 32);
            ldsm4(f1, Bg_t + b_off + 1280 + ks * 32);
#pragma unroll
            for (int mi = 0; mi < 2; mi++) {
                mma_tf32(dG[mi][0], a[mi], &f0[0]);
                mma_tf32(dG[mi][1], a[mi], &f0[2]);
                mma_tf32(dG[mi][2], a[mi], &f1[0]);
                mma_tf32(dG[mi][3], a[mi], &f1[2]);
            }
            ldsm4(f0, Bu_t + b_off + ks * 32);
            ldsm4(f1, Bu_t + b_off + 1280 + ks * 32);
#pragma unroll
            for (int mi = 0; mi < 2; mi++) {
                mma_tf32(dU[mi][0], a[mi], &f0[0]);
                mma_tf32(dU[mi][1], a[mi], &f0[2]);
                mma_tf32(dU[mi][2], a[mi], &f1[0]);
                mma_tf32(dU[mi][3], a[mi], &f1[2]);
            }
        }
        __syncthreads();
    }

    // epilogue: hmid = tf32_round( silu(G) * U * combine_weight ), packed rows
#pragma unroll
    for (int mi = 0; mi < 2; mi++) {
#pragma unroll
        for (int ni = 0; ni < 4; ni++) {
            int rr = wm + mi * 16 + gid;
            int cc = wn + ni * 8 + tig * 2;
#pragma unroll
            for (int q = 0; q < 4; q++) {
                int r = rr + (q >> 1) * 8;
                int c = cc + (q & 1);
                if (m0 + r < n_e) {
                    float g = dG[mi][ni][q], u = dU[mi][ni][q];
                    float s = g / (1.f + expf(-g));
                    g_hmid[(size_t)(base + m0 + r) * I_DIM + n0 + c] =
                        tf32r(s * u * rw[r]);
                }
            }
        }
    }
}

// ---------------- kernel 3: down grouped GEMM ----------------
// grid: (H/BN=16, 16, E=16), block 256. min-blocks=2 -> reg cap 128 -> 2 CTAs/SM.
__global__ void __launch_bounds__(256, 2) down_kernel()
{
    const int e = blockIdx.z;
    const int n_e = g_counts[e];
    const int m0 = blockIdx.y * BM;
    if (m0 >= n_e) return;
    const int base = g_off[e];
    const int n0 = blockIdx.x * BN;

    __shared__ float As[2][A_TB];
    __shared__ float Bs[2][B_TB];

    const int tid = threadIdx.x;
    const int warp = tid >> 5, lane = tid & 31;
    const int gid = lane >> 2, tig = lane & 3;
    const int wm = (warp >> 1) * 32, wn = (warp & 1) * 32;

    const uint32_t a_off = (uint32_t)((wm + (lane & 7) + ((lane >> 3) & 1) * 8) * STR * 4
                                      + ((lane >> 4) & 1) * 16);
    const uint32_t b_off = (uint32_t)((wn + (lane & 7) + ((lane >> 4) & 1) * 8) * STR * 4
                                      + ((lane >> 3) & 1) * 16);
    const uint32_t As_b = (uint32_t)__cvta_generic_to_shared(&As[0][0]);
    const uint32_t Bs_b = (uint32_t)__cvta_generic_to_shared(&Bs[0][0]);

    const float* Ain = g_hmid + (size_t)base * I_DIM;                   // packed rows
    const float* wdT = g_hmid + HM_WD + (size_t)e * H_DIM * I_DIM;      // [H, I] n-major

    float dD[2][4][4] = {};

    auto load_stage = [&](int kt, int buf) {
        const int k0 = kt * BK;
#pragma unroll
        for (int j = 0; j < 2; j++) {
            int idx = tid + 256 * j;
            int row = idx >> 2, c4 = idx & 3;
            cp16(&As[buf][row * STR + c4 * 4],
                 Ain + (size_t)(m0 + row) * I_DIM + k0 + c4 * 4);
        }
        {
            int row = tid >> 2, c4 = tid & 3;
            cp16(&Bs[buf][row * STR + c4 * 4],
                 wdT + (size_t)(n0 + row) * I_DIM + k0 + c4 * 4);
        }
        cp_commit();
    };

    const int KT = I_DIM / BK;  // 32
    load_stage(0, 0);

    for (int kt = 0; kt < KT; kt++) {
        int buf = kt & 1;
        if (kt + 1 < KT) { load_stage(kt + 1, buf ^ 1); cp_wait<1>(); }
        else             { cp_wait<0>(); }
        __syncthreads();

        const uint32_t As_t = As_b + (uint32_t)buf * (A_TB * 4);
        const uint32_t Bs_t = Bs_b + (uint32_t)buf * (B_TB * 4);

#pragma unroll
        for (int ks = 0; ks < 2; ks++) {
            uint32_t a[2][4];
            ldsm4(a[0], As_t + a_off + ks * 32);
            ldsm4(a[1], As_t + a_off + 1280 + ks * 32);
            uint32_t f0[4], f1[4];
            ldsm4(f0, Bs_t + b_off + ks * 32);
            ldsm4(f1, Bs_t + b_off + 1280 + ks * 32);
#pragma unroll
            for (int mi = 0; mi < 2; mi++) {
                mma_tf32(dD[mi][0], a[mi], &f0[0]);
                mma_tf32(dD[mi][1], a[mi], &f0[2]);
                mma_tf32(dD[mi][2], a[mi], &f1[0]);
                mma_tf32(dD[mi][3], a[mi], &f1[2]);
            }
        }
        __syncthreads();
    }

#pragma unroll
    for (int mi = 0; mi < 2; mi++) {
#pragma unroll
        for (int ni = 0; ni < 4; ni++) {
            int rr = wm + mi * 16 + gid;
            int cc = wn + ni * 8 + tig * 2;
#pragma unroll
            for (int q = 0; q < 4; q++) {
                int r = rr + (q >> 1) * 8;
                int c = cc + (q & 1);
                if (m0 + r < n_e)
                    g_Y[(size_t)(base + m0 + r) * H_DIM + n0 + c] = dD[mi][ni][q];
            }
        }
    }
}

// ---------------- kernel 4: per-token combine ----------------
__global__ void __launch_bounds__(256) combine_kernel(float* __restrict__ out)
{
    const int t = blockIdx.x;
    __shared__ int slots[TOPK];
    if (threadIdx.x < TOPK) slots[threadIdx.x] = g_slot[t * TOPK + threadIdx.x];
    __syncthreads();

    int h4 = threadIdx.x;  // 256 float4 per token (H=1024)
    float4 acc = make_float4(0.f, 0.f, 0.f, 0.f);
#pragma unroll
    for (int k = 0; k < TOPK; k++) {
        const float4* y = (const float4*)(g_Y + (size_t)slots[k] * H_DIM);
        float4 v = y[h4];
        acc.x += v.x; acc.y += v.y; acc.z += v.z; acc.w += v.w;
    }
    ((float4*)out)[(size_t)t * (H_DIM / 4) + h4] = acc;
}

// ---------------- launch ----------------
extern "C" void kernel_launch(void* const* d_in, const int* in_sizes, int n_in,
                              void* d_out, int out_size)
{
    const float* x      = (const float*)d_in[0];  // [2,1024,1024]
    const float* gate_w = (const float*)d_in[1];  // [1024,16]
    const float* w_gate = (const float*)d_in[2];  // [16,1024,512]
    const float* w_up   = (const float*)d_in[3];  // [16,1024,512]
    const float* w_down = (const float*)d_in[4];  // [16,512,1024]
    float* out = (float*)d_out;

    float* logits = nullptr;
    if (out_size >= T_TOK * H_DIM + T_TOK * N_EXP)
        logits = out + (size_t)T_TOK * H_DIM;

    init_kernel<<<1, 32>>>();
    xcvt_kernel<<<(T_TOK * H_DIM / 4) / 256, 256>>>(x);
    transpose_kernel<<<dim3(I_DIM / 32, H_DIM / 32, N_EXP), dim3(32, 8)>>>(w_gate, H_DIM, I_DIM, 0);
    transpose_kernel<<<dim3(I_DIM / 32, H_DIM / 32, N_EXP), dim3(32, 8)>>>(w_up,   H_DIM, I_DIM, 1);
    transpose_kernel<<<dim3(H_DIM / 32, I_DIM / 32, N_EXP), dim3(32, 8)>>>(w_down, I_DIM, H_DIM, 2);
    router_kernel<<<T_TOK / 8, 256>>>(x, gate_w, logits);
    offsets_kernel<<<1, 32>>>();
    scatter_kernel<<<TROWS / 256, 256>>>();
    gu_kernel<<<dim3(I_DIM / BN, 16, N_EXP), 256>>>();
    down_kernel<<<dim3(H_DIM / BN, 16, N_EXP), 256>>>();
    combine_kernel<<<T_TOK, 256>>>(out);
}

// round 12
// speedup vs baseline: 1.2103x; 1.0374x over previous
#include <cuda_runtime.h>
#include <cstdint>
#include <math.h>

// Qwen3MoeSparseMoeBlock: B=2,S=1024 -> T=2048 tokens
#define T_TOK 2048
#define H_DIM 1024
#define I_DIM 512
#define N_EXP 16
#define TOPK  8
#define TROWS (T_TOK * TOPK)     // 16384 total routed rows (packed)

// ---------------- scratch (static device globals; total ~136 MB, known-good) ----------
__device__ int   g_counts[N_EXP];
__device__ int   g_off[N_EXP];                 // packed start row per expert
__device__ int   g_ep[TROWS];                  // (t,k) -> (e<<16)|pos
__device__ int   g_rows[TROWS];                // packed row -> token id
__device__ int   g_slot[TROWS];                // (t,k) -> packed row id
__device__ float g_combine[T_TOK * N_EXP];     // dense combine weights
__device__ float g_xt[T_TOK * H_DIM];          // tf32-rounded x (8 MB)
// g_hmid: [0, 8388608)  = packed hmid  [16384 x 512]   (32 MB)
//         [8388608, 2x) = w_down^T     [E,H,I] tf32    (32 MB)
__device__ float g_hmid[2 * 8388608];
// g_Y: prepass phase:  [0, 8388608) = w_gate^T [E,I,H]; [8388608, 2x) = w_up^T (64 MB)
//      output phase:   packed Y [16384 x 1024]          (64 MB, overwrites weights)
__device__ float g_Y[2 * 8388608];
#define HM_WD  8388608
#define Y_WU   8388608

// ---------------- PTX helpers ----------------
__device__ __forceinline__ uint32_t f2tf32(float f) {
    uint32_t r;
    asm volatile("cvt.rna.tf32.f32 %0, %1;\n" : "=r"(r) : "f"(f));
    return r;
}
__device__ __forceinline__ float tf32r(float f) { return __uint_as_float(f2tf32(f)); }

// mma.sync tf32: operands are raw 32-bit regs holding tf32-prerounded floats.
__device__ __forceinline__ void mma_tf32(float* d, const uint32_t* a, const uint32_t* b) {
    asm volatile(
        "mma.sync.aligned.m16n8k8.row.col.f32.tf32.tf32.f32 "
        "{%0,%1,%2,%3}, {%4,%5,%6,%7}, {%8,%9}, {%0,%1,%2,%3};\n"
        : "+f"(d[0]), "+f"(d[1]), "+f"(d[2]), "+f"(d[3])
        : "r"(a[0]), "r"(a[1]), "r"(a[2]), "r"(a[3]), "r"(b[0]), "r"(b[1]));
}

// ldmatrix x4 (b16): four 8x8 b16 tiles == four 8x4 tf32 tiles (exact tf32 frag layout)
__device__ __forceinline__ void ldsm4(uint32_t* r, uint32_t addr) {
    asm volatile("ldmatrix.sync.aligned.m8n8.x4.shared.b16 {%0,%1,%2,%3}, [%4];"
                 : "=r"(r[0]), "=r"(r[1]), "=r"(r[2]), "=r"(r[3]) : "r"(addr));
}

__device__ __forceinline__ void cp16(void* smem_dst, const void* gsrc) {
    uint32_t d = (uint32_t)__cvta_generic_to_shared(smem_dst);
    asm volatile("cp.async.cg.shared.global [%0], [%1], 16;\n" :: "r"(d), "l"(gsrc));
}
__device__ __forceinline__ void cp_commit() { asm volatile("cp.async.commit_group;\n"); }
template <int N>
__device__ __forceinline__ void cp_wait() { asm volatile("cp.async.wait_group %0;\n" :: "n"(N)); }

// ---------------- launch 1: x -> tf32-rounded copy (+ counter init) ----------------
__global__ void __launch_bounds__(256) xcvt_kernel(const float* __restrict__ x) {
    if (blockIdx.x == 0 && threadIdx.x < N_EXP) g_counts[threadIdx.x] = 0;
    int i = blockIdx.x * 256 + threadIdx.x;
    float4 v = ((const float4*)x)[i];
    v.x = tf32r(v.x); v.y = tf32r(v.y); v.z = tf32r(v.z); v.w = tf32r(v.w);
    ((float4*)g_xt)[i] = v;
}

// ---------------- launch 2: all three weight transposes in one kernel --------------
// blockIdx.z: [0,16) w_gate, [16,32) w_up, [32,48) w_down.  src [R,C] -> dst [C,R].
__global__ void __launch_bounds__(256) transpose_all_kernel(
    const float* __restrict__ wg, const float* __restrict__ wu,
    const float* __restrict__ wd)
{
    __shared__ float s[32][33];
    const int z = blockIdx.z;
    const int mode = z >> 4, e = z & 15;
    const int R = (mode < 2) ? H_DIM : I_DIM;
    const int C = (mode < 2) ? I_DIM : H_DIM;
    const int c0 = blockIdx.x * 32, r0 = blockIdx.y * 32;
    if (c0 >= C || r0 >= R) return;
    const float* S = ((mode == 0) ? wg : (mode == 1) ? wu : wd) + (size_t)e * R * C;
    float* D = ((mode == 0) ? g_Y : (mode == 1) ? (g_Y + Y_WU) : (g_hmid + HM_WD))
               + (size_t)e * R * C;
    const int tx = threadIdx.x, ty = threadIdx.y;
#pragma unroll
    for (int j = 0; j < 4; j++)
        s[ty + j * 8][tx] = S[(size_t)(r0 + ty + j * 8) * C + c0 + tx];
    __syncthreads();
#pragma unroll
    for (int j = 0; j < 4; j++)
        D[(size_t)(c0 + ty + j * 8) * R + r0 + tx] = tf32r(s[tx][ty + j * 8]);
}

// ---------------- launch 3: router (logits, top-8, per-expert counts) --------------
__global__ void __launch_bounds__(256) router_kernel(
    const float* __restrict__ x, const float* __restrict__ gw,
    float* __restrict__ logits_out)
{
    const int warp = threadIdx.x >> 5, lane = threadIdx.x & 31;
    const int t = blockIdx.x * 8 + warp;
    const float* xr = x + (size_t)t * H_DIM;

    float acc[N_EXP];
#pragma unroll
    for (int e = 0; e < N_EXP; e++) acc[e] = 0.f;

    for (int i = 0; i < H_DIM / 32; i++) {
        int h = i * 32 + lane;
        float xv = xr[h];
        const float* g = gw + (size_t)h * N_EXP;
#pragma unroll
        for (int e = 0; e < N_EXP; e++) acc[e] = fmaf(xv, g[e], acc[e]);
    }
#pragma unroll
    for (int e = 0; e < N_EXP; e++) {
#pragma unroll
        for (int off = 16; off; off >>= 1)
            acc[e] += __shfl_xor_sync(0xFFFFFFFFu, acc[e], off);
    }

    if (lane == 0) {
        if (logits_out) {
#pragma unroll
            for (int e = 0; e < N_EXP; e++) logits_out[t * N_EXP + e] = acc[e];
        }
        float m = acc[0];
#pragma unroll
        for (int e = 1; e < N_EXP; e++) m = fmaxf(m, acc[e]);

        unsigned sel = 0;
        int   idx[TOPK];
        float w[TOPK];
        float ssum = 0.f;
#pragma unroll
        for (int k = 0; k < TOPK; k++) {
            float best = -3.0e38f; int bi = 0;
#pragma unroll
            for (int e = 0; e < N_EXP; e++) {
                if (!((sel >> e) & 1u) && acc[e] > best) { best = acc[e]; bi = e; }
            }
            sel |= (1u << bi);
            idx[k] = bi;
            w[k] = expf(acc[bi] - m);
            ssum += w[k];
        }
        float inv = 1.f / ssum;
#pragma unroll
        for (int e = 0; e < N_EXP; e++) {
            float ce = 0.f;
#pragma unroll
            for (int k = 0; k < TOPK; k++)
                ce += (idx[k] == e) ? w[k] * inv : 0.f;
            g_combine[t * N_EXP + e] = ce;
        }

#pragma unroll
        for (int k = 0; k < TOPK; k++) {
            int e = idx[k];
            int pos = atomicAdd(&g_counts[e], 1);
            g_ep[t * TOPK + k] = (e << 16) | pos;
        }
    }
}

// ---------------- launch 4: exclusive prefix offsets ----------------
__global__ void offsets_kernel() {
    if (threadIdx.x == 0) {
        int run = 0;
#pragma unroll
        for (int e = 0; e < N_EXP; e++) { g_off[e] = run; run += g_counts[e]; }
    }
}

// ---------------- launch 5: scatter packed row lists ----------------
__global__ void __launch_bounds__(256) scatter_kernel() {
    int i = blockIdx.x * 256 + threadIdx.x;   // i in [0, TROWS)
    int ep = g_ep[i];
    int row = g_off[ep >> 16] + (ep & 0xFFFF);
    g_rows[row] = i / TOPK;
    g_slot[i] = row;
}

// ---------------- GEMM tiling ----------------
// CTA tile 128x64, BK=16, 8 warps (4x2), warp tile 32x32, 3-stage cp.async pipeline.
// smem padded: row stride 20 floats (80B) -> conflict-free ldmatrix phases.
#define BM 128
#define BN 64
#define BK 16
#define STR 20                   // floats per smem row
#define A_TB (BM * STR)          // 2560 floats = 10240 B per A stage
#define B_TB (BN * STR)          // 1280 floats =  5120 B per B stage
#define A_SB (A_TB * 4)
#define B_SB (B_TB * 4)
// gu dynamic smem layout: A[3] | Bg[3] | Bu[3] | rtok[128] | rw[128]
#define GU_OFF_BG (3 * A_SB)                 // 30720
#define GU_OFF_BU (GU_OFF_BG + 3 * B_SB)     // 46080
#define GU_OFF_TK (GU_OFF_BU + 3 * B_SB)     // 61440
#define GU_OFF_RW (GU_OFF_TK + 512)          // 61952
#define GU_SMEM   (GU_OFF_RW + 512)          // 62464

// ---------------- launch 6: fused gate+up grouped GEMM + SiLU epilogue -------------
// grid: (I/BN=8, 16, E=16), block 256, minBlocks=2 -> reg cap 128 -> 2 CTAs/SM.
__global__ void __launch_bounds__(256, 2) gu_kernel()
{
    extern __shared__ char dsm[];
    const int e = blockIdx.z;
    const int n_e = g_counts[e];
    const int m0 = blockIdx.y * BM;
    if (m0 >= n_e) return;
    const int base = g_off[e];
    const int n0 = blockIdx.x * BN;

    float* As   = (float*)dsm;
    float* Bg   = (float*)(dsm + GU_OFF_BG);
    float* Bu   = (float*)(dsm + GU_OFF_BU);
    int*   rtok = (int*)  (dsm + GU_OFF_TK);
    float* rw   = (float*)(dsm + GU_OFF_RW);

    const int tid = threadIdx.x;
    if (tid < BM) {
        int r = m0 + tid;
        int tok = 0; float w = 0.f;
        if (r < n_e) { tok = g_rows[base + r]; w = g_combine[tok * N_EXP + e]; }
        rtok[tid] = tok; rw[tid] = w;
    }
    __syncthreads();

    const int warp = tid >> 5, lane = tid & 31;
    const int gid = lane >> 2, tig = lane & 3;
    const int wm = (warp >> 1) * 32, wn = (warp & 1) * 32;

    const uint32_t a_off = (uint32_t)((wm + (lane & 7) + ((lane >> 3) & 1) * 8) * STR * 4
                                      + ((lane >> 4) & 1) * 16);
    const uint32_t b_off = (uint32_t)((wn + (lane & 7) + ((lane >> 4) & 1) * 8) * STR * 4
                                      + ((lane >> 3) & 1) * 16);
    const uint32_t sm_b = (uint32_t)__cvta_generic_to_shared(dsm);

    const float* wgT = g_Y + (size_t)e * I_DIM * H_DIM;           // [I, H] n-major
    const float* wuT = g_Y + Y_WU + (size_t)e * I_DIM * H_DIM;

    float dG[2][4][4] = {}, dU[2][4][4] = {};

    auto load_stage = [&](int kt, int b) {
        const int k0 = kt * BK;
        float* Ab = As + b * A_TB;
        float* Gb = Bg + b * B_TB;
        float* Ub = Bu + b * B_TB;
#pragma unroll
        for (int j = 0; j < 2; j++) {
            int idx = tid + 256 * j;              // 512 chunks = 128 rows x 4
            int row = idx >> 2, c4 = idx & 3;
            cp16(Ab + row * STR + c4 * 4,
                 g_xt + (size_t)rtok[row] * H_DIM + k0 + c4 * 4);
        }
        {
            int row = tid >> 2, c4 = tid & 3;     // 256 chunks = 64 rows x 4
            cp16(Gb + row * STR + c4 * 4,
                 wgT + (size_t)(n0 + row) * H_DIM + k0 + c4 * 4);
            cp16(Ub + row * STR + c4 * 4,
                 wuT + (size_t)(n0 + row) * H_DIM + k0 + c4 * 4);
        }
        cp_commit();
    };

    const int KT = H_DIM / BK;  // 64
    load_stage(0, 0);
    load_stage(1, 1);

    int bc = 0, bl = 2;   // compute buffer, load buffer ((kt+2)%3)
    for (int kt = 0; kt < KT; kt++) {
        if (kt + 1 < KT) cp_wait<1>(); else cp_wait<0>();
        __syncthreads();                       // single barrier per K-step
        if (kt + 2 < KT) load_stage(kt + 2, bl);

        const uint32_t As_t = sm_b + (uint32_t)bc * A_SB;
        const uint32_t Bg_t = sm_b + GU_OFF_BG + (uint32_t)bc * B_SB;
        const uint32_t Bu_t = sm_b + GU_OFF_BU + (uint32_t)bc * B_SB;

#pragma unroll
        for (int ks = 0; ks < 2; ks++) {
            uint32_t a[2][4];
            ldsm4(a[0], As_t + a_off + ks * 32);
            ldsm4(a[1], As_t + a_off + 1280 + ks * 32);   // +16 rows * 80B
            uint32_t f0[4], f1[4];
            ldsm4(f0, Bg_t + b_off + ks * 32);
            ldsm4(f1, Bg_t + b_off + 1280 + ks * 32);
#pragma unroll
            for (int mi = 0; mi < 2; mi++) {
                mma_tf32(dG[mi][0], a[mi], &f0[0]);
                mma_tf32(dG[mi][1], a[mi], &f0[2]);
                mma_tf32(dG[mi][2], a[mi], &f1[0]);
                mma_tf32(dG[mi][3], a[mi], &f1[2]);
            }
            ldsm4(f0, Bu_t + b_off + ks * 32);
            ldsm4(f1, Bu_t + b_off + 1280 + ks * 32);
#pragma unroll
            for (int mi = 0; mi < 2; mi++) {
                mma_tf32(dU[mi][0], a[mi], &f0[0]);
                mma_tf32(dU[mi][1], a[mi], &f0[2]);
                mma_tf32(dU[mi][2], a[mi], &f1[0]);
                mma_tf32(dU[mi][3], a[mi], &f1[2]);
            }
        }
        bc = (bc == 2) ? 0 : bc + 1;
        bl = (bl == 2) ? 0 : bl + 1;
    }

    // epilogue: hmid = tf32_round( silu(G) * U * combine_weight ), packed rows
#pragma unroll
    for (int mi = 0; mi < 2; mi++) {
#pragma unroll
        for (int ni = 0; ni < 4; ni++) {
            int rr = wm + mi * 16 + gid;
            int cc = wn + ni * 8 + tig * 2;
#pragma unroll
            for (int q = 0; q < 4; q++) {
                int r = rr + (q >> 1) * 8;
                int c = cc + (q & 1);
                if (m0 + r < n_e) {
                    float g = dG[mi][ni][q], u = dU[mi][ni][q];
                    float s = g / (1.f + expf(-g));
                    g_hmid[(size_t)(base + m0 + r) * I_DIM + n0 + c] =
                        tf32r(s * u * rw[r]);
                }
            }
        }
    }
}

// ---------------- launch 7: down grouped GEMM (3-stage, static smem 45KB) ----------
__global__ void __launch_bounds__(256, 2) down_kernel()
{
    const int e = blockIdx.z;
    const int n_e = g_counts[e];
    const int m0 = blockIdx.y * BM;
    if (m0 >= n_e) return;
    const int base = g_off[e];
    const int n0 = blockIdx.x * BN;

    __shared__ float As[3][A_TB];
    __shared__ float Bs[3][B_TB];

    const int tid = threadIdx.x;
    const int warp = tid >> 5, lane = tid & 31;
    const int gid = lane >> 2, tig = lane & 3;
    const int wm = (warp >> 1) * 32, wn = (warp & 1) * 32;

    const uint32_t a_off = (uint32_t)((wm + (lane & 7) + ((lane >> 3) & 1) * 8) * STR * 4
                                      + ((lane >> 4) & 1) * 16);
    const uint32_t b_off = (uint32_t)((wn + (lane & 7) + ((lane >> 4) & 1) * 8) * STR * 4
                                      + ((lane >> 3) & 1) * 16);
    const uint32_t As_b = (uint32_t)__cvta_generic_to_shared(&As[0][0]);
    const uint32_t Bs_b = (uint32_t)__cvta_generic_to_shared(&Bs[0][0]);

    const float* Ain = g_hmid + (size_t)base * I_DIM;                   // packed rows
    const float* wdT = g_hmid + HM_WD + (size_t)e * H_DIM * I_DIM;      // [H, I] n-major

    float dD[2][4][4] = {};

    auto load_stage = [&](int kt, int b) {
        const int k0 = kt * BK;
#pragma unroll
        for (int j = 0; j < 2; j++) {
            int idx = tid + 256 * j;
            int row = idx >> 2, c4 = idx & 3;
            cp16(&As[b][row * STR + c4 * 4],
                 Ain + (size_t)(m0 + row) * I_DIM + k0 + c4 * 4);
        }
        {
            int row = tid >> 2, c4 = tid & 3;
            cp16(&Bs[b][row * STR + c4 * 4],
                 wdT + (size_t)(n0 + row) * I_DIM + k0 + c4 * 4);
        }
        cp_commit();
    };

    const int KT = I_DIM / BK;  // 32
    load_stage(0, 0);
    load_stage(1, 1);

    int bc = 0, bl = 2;
    for (int kt = 0; kt < KT; kt++) {
        if (kt + 1 < KT) cp_wait<1>(); else cp_wait<0>();
        __syncthreads();
        if (kt + 2 < KT) load_stage(kt + 2, bl);

        const uint32_t As_t = As_b + (uint32_t)bc * A_SB;
        const uint32_t Bs_t = Bs_b + (uint32_t)bc * B_SB;

#pragma unroll
        for (int ks = 0; ks < 2; ks++) {
            uint32_t a[2][4];
            ldsm4(a[0], As_t + a_off + ks * 32);
            ldsm4(a[1], As_t + a_off + 1280 + ks * 32);
            uint32_t f0[4], f1[4];
            ldsm4(f0, Bs_t + b_off + ks * 32);
            ldsm4(f1, Bs_t + b_off + 1280 + ks * 32);
#pragma unroll
            for (int mi = 0; mi < 2; mi++) {
                mma_tf32(dD[mi][0], a[mi], &f0[0]);
                mma_tf32(dD[mi][1], a[mi], &f0[2]);
                mma_tf32(dD[mi][2], a[mi], &f1[0]);
                mma_tf32(dD[mi][3], a[mi], &f1[2]);
            }
        }
        bc = (bc == 2) ? 0 : bc + 1;
        bl = (bl == 2) ? 0 : bl + 1;
    }

#pragma unroll
    for (int mi = 0; mi < 2; mi++) {
#pragma unroll
        for (int ni = 0; ni < 4; ni++) {
            int rr = wm + mi * 16 + gid;
            int cc = wn + ni * 8 + tig * 2;
#pragma unroll
            for (int q = 0; q < 4; q++) {
                int r = rr + (q >> 1) * 8;
                int c = cc + (q & 1);
                if (m0 + r < n_e)
                    g_Y[(size_t)(base + m0 + r) * H_DIM + n0 + c] = dD[mi][ni][q];
            }
        }
    }
}

// ---------------- launch 8: per-token combine ----------------
__global__ void __launch_bounds__(256) combine_kernel(float* __restrict__ out)
{
    const int t = blockIdx.x;
    __shared__ int slots[TOPK];
    if (threadIdx.x < TOPK) slots[threadIdx.x] = g_slot[t * TOPK + threadIdx.x];
    __syncthreads();

    int h4 = threadIdx.x;  // 256 float4 per token (H=1024)
    float4 acc = make_float4(0.f, 0.f, 0.f, 0.f);
#pragma unroll
    for (int k = 0; k < TOPK; k++) {
        const float4* y = (const float4*)(g_Y + (size_t)slots[k] * H_DIM);
        float4 v = y[h4];
        acc.x += v.x; acc.y += v.y; acc.z += v.z; acc.w += v.w;
    }
    ((float4*)out)[(size_t)t * (H_DIM / 4) + h4] = acc;
}

// ---------------- launch ----------------
extern "C" void kernel_launch(void* const* d_in, const int* in_sizes, int n_in,
                              void* d_out, int out_size)
{
    const float* x      = (const float*)d_in[0];  // [2,1024,1024]
    const float* gate_w = (const float*)d_in[1];  // [1024,16]
    const float* w_gate = (const float*)d_in[2];  // [16,1024,512]
    const float* w_up   = (const float*)d_in[3];  // [16,1024,512]
    const float* w_down = (const float*)d_in[4];  // [16,512,1024]
    float* out = (float*)d_out;

    float* logits = nullptr;
    if (out_size >= T_TOK * H_DIM + T_TOK * N_EXP)
        logits = out + (size_t)T_TOK * H_DIM;

    cudaFuncSetAttribute(gu_kernel, cudaFuncAttributeMaxDynamicSharedMemorySize, GU_SMEM);

    xcvt_kernel<<<(T_TOK * H_DIM / 4) / 256, 256>>>(x);                       // launch 1
    transpose_all_kernel<<<dim3(32, 32, 48), dim3(32, 8)>>>(w_gate, w_up, w_down); // 2
    router_kernel<<<T_TOK / 8, 256>>>(x, gate_w, logits);                     // 3
    offsets_kernel<<<1, 32>>>();                                              // 4
    scatter_kernel<<<TROWS / 256, 256>>>();                                   // 5
    gu_kernel<<<dim3(I_DIM / BN, 16, N_EXP), 256, GU_SMEM>>>();               // 6 (ncu)
    down_kernel<<<dim3(H_DIM / BN, 16, N_EXP), 256>>>();                      // 7
    combine_kernel<<<T_TOK, 256>>>(out);                                      // 8
}

// round 13
// speedup vs baseline: 1.3342x; 1.1024x over previous
#include <cuda_runtime.h>
#include <cstdint>
#include <math.h>

// Qwen3MoeSparseMoeBlock: B=2,S=1024 -> T=2048 tokens
#define T_TOK 2048
#define H_DIM 1024
#define I_DIM 512
#define N_EXP 16
#define TOPK  8
#define TROWS (T_TOK * TOPK)     // 16384 total routed rows (packed)

// ---------------- scratch (static device globals; total ~136 MB, known-good) ----------
__device__ int   g_counts[N_EXP];
__device__ int   g_off[N_EXP];                 // packed start row per expert
__device__ int   g_ep[TROWS];                  // (t,k) -> (e<<16)|pos
__device__ int   g_rows[TROWS];                // packed row -> token id
__device__ int   g_slot[TROWS];                // (t,k) -> packed row id
__device__ float g_combine[T_TOK * N_EXP];     // dense combine weights
__device__ float g_xt[T_TOK * H_DIM];          // tf32-rounded x (8 MB)
// g_hmid: [0, 8388608)  = packed hmid  [16384 x 512]   (32 MB)
//         [8388608, 2x) = w_down^T     [E,H,I] tf32    (32 MB)
__device__ float g_hmid[2 * 8388608];
// g_Y: prepass phase:  [0, 8388608) = w_gate^T [E,I,H]; [8388608, 2x) = w_up^T (64 MB)
//      output phase:   packed Y [16384 x 1024]          (64 MB, overwrites weights)
__device__ float g_Y[2 * 8388608];
#define HM_WD  8388608
#define Y_WU   8388608

// ---------------- PTX helpers ----------------
__device__ __forceinline__ uint32_t f2tf32(float f) {
    uint32_t r;
    asm volatile("cvt.rna.tf32.f32 %0, %1;\n" : "=r"(r) : "f"(f));
    return r;
}
__device__ __forceinline__ float tf32r(float f) { return __uint_as_float(f2tf32(f)); }

// mma.sync tf32: operands are raw 32-bit regs holding tf32-prerounded floats.
__device__ __forceinline__ void mma_tf32(float* d, const uint32_t* a, const uint32_t* b) {
    asm volatile(
        "mma.sync.aligned.m16n8k8.row.col.f32.tf32.tf32.f32 "
        "{%0,%1,%2,%3}, {%4,%5,%6,%7}, {%8,%9}, {%0,%1,%2,%3};\n"
        : "+f"(d[0]), "+f"(d[1]), "+f"(d[2]), "+f"(d[3])
        : "r"(a[0]), "r"(a[1]), "r"(a[2]), "r"(a[3]), "r"(b[0]), "r"(b[1]));
}

// ldmatrix x4 (b16): four 8x8 b16 tiles == four 8x4 tf32 tiles (exact tf32 frag layout)
__device__ __forceinline__ void ldsm4(uint32_t* r, uint32_t addr) {
    asm volatile("ldmatrix.sync.aligned.m8n8.x4.shared.b16 {%0,%1,%2,%3}, [%4];"
                 : "=r"(r[0]), "=r"(r[1]), "=r"(r[2]), "=r"(r[3]) : "r"(addr));
}

__device__ __forceinline__ void cp16(void* smem_dst, const void* gsrc) {
    uint32_t d = (uint32_t)__cvta_generic_to_shared(smem_dst);
    asm volatile("cp.async.cg.shared.global [%0], [%1], 16;\n" :: "r"(d), "l"(gsrc));
}
__device__ __forceinline__ void cp_commit() { asm volatile("cp.async.commit_group;\n"); }
template <int N>
__device__ __forceinline__ void cp_wait() { asm volatile("cp.async.wait_group %0;\n" :: "n"(N)); }

// ---------------- launch 1: fused prepass (counter init + x cvt + 3 transposes) ----
// blockIdx.z: [0,16) w_gate, [16,32) w_up, [32,48) w_down, z==48: xcvt.
__global__ void __launch_bounds__(256) prep_kernel(
    const float* __restrict__ x, const float* __restrict__ wg,
    const float* __restrict__ wu, const float* __restrict__ wd)
{
    const int z = blockIdx.z;
    const int tx = threadIdx.x, ty = threadIdx.y;
    const int tid = ty * 32 + tx;
    if (z == 48) {
        if (blockIdx.x == 0 && blockIdx.y == 0 && tid < N_EXP) g_counts[tid] = 0;
        int bid = blockIdx.y * 32 + blockIdx.x;       // 1024 blocks
        int i = (bid * 256 + tid) * 2;                // 2 float4 per thread
#pragma unroll
        for (int j = 0; j < 2; j++) {
            float4 v = ((const float4*)x)[i + j];
            v.x = tf32r(v.x); v.y = tf32r(v.y); v.z = tf32r(v.z); v.w = tf32r(v.w);
            ((float4*)g_xt)[i + j] = v;
        }
        return;
    }
    __shared__ float s[32][33];
    const int mode = z >> 4, e = z & 15;
    const int R = (mode < 2) ? H_DIM : I_DIM;
    const int C = (mode < 2) ? I_DIM : H_DIM;
    const int c0 = blockIdx.x * 32, r0 = blockIdx.y * 32;
    if (c0 >= C || r0 >= R) return;
    const float* S = ((mode == 0) ? wg : (mode == 1) ? wu : wd) + (size_t)e * R * C;
    float* D = ((mode == 0) ? g_Y : (mode == 1) ? (g_Y + Y_WU) : (g_hmid + HM_WD))
               + (size_t)e * R * C;
#pragma unroll
    for (int j = 0; j < 4; j++)
        s[ty + j * 8][tx] = S[(size_t)(r0 + ty + j * 8) * C + c0 + tx];
    __syncthreads();
#pragma unroll
    for (int j = 0; j < 4; j++)
        D[(size_t)(c0 + ty + j * 8) * R + r0 + tx] = tf32r(s[tx][ty + j * 8]);
}

// ---------------- launch 2: router (logits, top-8, per-expert counts) --------------
__global__ void __launch_bounds__(256) router_kernel(
    const float* __restrict__ x, const float* __restrict__ gw,
    float* __restrict__ logits_out)
{
    const int warp = threadIdx.x >> 5, lane = threadIdx.x & 31;
    const int t = blockIdx.x * 8 + warp;
    const float* xr = x + (size_t)t * H_DIM;

    float acc[N_EXP];
#pragma unroll
    for (int e = 0; e < N_EXP; e++) acc[e] = 0.f;

    for (int i = 0; i < H_DIM / 32; i++) {
        int h = i * 32 + lane;
        float xv = xr[h];
        const float* g = gw + (size_t)h * N_EXP;
#pragma unroll
        for (int e = 0; e < N_EXP; e++) acc[e] = fmaf(xv, g[e], acc[e]);
    }
#pragma unroll
    for (int e = 0; e < N_EXP; e++) {
#pragma unroll
        for (int off = 16; off; off >>= 1)
            acc[e] += __shfl_xor_sync(0xFFFFFFFFu, acc[e], off);
    }

    if (lane == 0) {
        if (logits_out) {
#pragma unroll
            for (int e = 0; e < N_EXP; e++) logits_out[t * N_EXP + e] = acc[e];
        }
        float m = acc[0];
#pragma unroll
        for (int e = 1; e < N_EXP; e++) m = fmaxf(m, acc[e]);

        unsigned sel = 0;
        int   idx[TOPK];
        float w[TOPK];
        float ssum = 0.f;
#pragma unroll
        for (int k = 0; k < TOPK; k++) {
            float best = -3.0e38f; int bi = 0;
#pragma unroll
            for (int e = 0; e < N_EXP; e++) {
                if (!((sel >> e) & 1u) && acc[e] > best) { best = acc[e]; bi = e; }
            }
            sel |= (1u << bi);
            idx[k] = bi;
            w[k] = expf(acc[bi] - m);
            ssum += w[k];
        }
        float inv = 1.f / ssum;
#pragma unroll
        for (int e = 0; e < N_EXP; e++) {
            float ce = 0.f;
#pragma unroll
            for (int k = 0; k < TOPK; k++)
                ce += (idx[k] == e) ? w[k] * inv : 0.f;
            g_combine[t * N_EXP + e] = ce;
        }

#pragma unroll
        for (int k = 0; k < TOPK; k++) {
            int e = idx[k];
            int pos = atomicAdd(&g_counts[e], 1);
            g_ep[t * TOPK + k] = (e << 16) | pos;
        }
    }
}

// ---------------- launch 3: scatter packed row lists (inline prefix offsets) -------
__global__ void __launch_bounds__(256) scatter_kernel() {
    __shared__ int soff[N_EXP];
    const int tid = threadIdx.x;
    if (tid < N_EXP) {
        int run = 0;
        for (int j = 0; j < tid; j++) run += g_counts[j];
        soff[tid] = run;
        if (blockIdx.x == 0) g_off[tid] = run;
    }
    __syncthreads();
    int i = blockIdx.x * 256 + tid;   // i in [0, TROWS)
    int ep = g_ep[i];
    int row = soff[ep >> 16] + (ep & 0xFFFF);
    g_rows[row] = i / TOPK;
    g_slot[i] = row;
}

// ---------------- GEMM tiling ----------------
// CTA tile 128x64, BK=32, 8 warps (4x2), warp tile 32x32, 3-stage cp.async pipeline.
// smem rows of 36 floats (144B): 4r mod 32 bank start -> conflict-free ldmatrix.
#define BM 128
#define BN 64
#define BK 32
#define STR 36                   // floats per smem row
#define A_TB (BM * STR)          // 4608 floats = 18432 B per A stage
#define B_TB (BN * STR)          // 2304 floats =  9216 B per B stage
#define A_SB (A_TB * 4)
#define B_SB (B_TB * 4)
#define ROW16 (16 * STR * 4)     // byte offset of +16 rows = 2304
// gu dynamic smem: A[3] | Bg[3] | Bu[3] | rtok[128] | rw[128]
#define GU_OFF_BG (3 * A_SB)                 // 55296
#define GU_OFF_BU (GU_OFF_BG + 3 * B_SB)     // 82944
#define GU_OFF_TK (GU_OFF_BU + 3 * B_SB)     // 110592
#define GU_OFF_RW (GU_OFF_TK + 512)
#define GU_SMEM   (GU_OFF_RW + 512)          // 111616 (x2 CTAs = 223 KB/SM, fits)
// down dynamic smem: A[3] | B[3]
#define DN_OFF_B  (3 * A_SB)
#define DN_SMEM   (DN_OFF_B + 3 * B_SB)      // 82944

// ---------------- launch 4 (ncu slot): fused gate+up grouped GEMM + SiLU -----------
// grid: (I/BN=8, 16, E=16), block 256, minBlocks=2 -> reg cap 128 -> 2 CTAs/SM.
__global__ void __launch_bounds__(256, 2) gu_kernel()
{
    extern __shared__ char dsm[];
    const int e = blockIdx.z;
    const int n_e = g_counts[e];
    const int m0 = blockIdx.y * BM;
    if (m0 >= n_e) return;
    const int base = g_off[e];
    const int n0 = blockIdx.x * BN;

    float* As   = (float*)dsm;
    float* Bg   = (float*)(dsm + GU_OFF_BG);
    float* Bu   = (float*)(dsm + GU_OFF_BU);
    int*   rtok = (int*)  (dsm + GU_OFF_TK);
    float* rw   = (float*)(dsm + GU_OFF_RW);

    const int tid = threadIdx.x;
    if (tid < BM) {
        int r = m0 + tid;
        int tok = 0; float w = 0.f;
        if (r < n_e) { tok = g_rows[base + r]; w = g_combine[tok * N_EXP + e]; }
        rtok[tid] = tok; rw[tid] = w;
    }
    __syncthreads();

    const int warp = tid >> 5, lane = tid & 31;
    const int gid = lane >> 2, tig = lane & 3;
    const int wm = (warp >> 1) * 32, wn = (warp & 1) * 32;

    const uint32_t a_off = (uint32_t)((wm + (lane & 7) + ((lane >> 3) & 1) * 8) * STR * 4
                                      + ((lane >> 4) & 1) * 16);
    const uint32_t b_off = (uint32_t)((wn + (lane & 7) + ((lane >> 4) & 1) * 8) * STR * 4
                                      + ((lane >> 3) & 1) * 16);
    const uint32_t sm_b = (uint32_t)__cvta_generic_to_shared(dsm);

    const float* wgT = g_Y + (size_t)e * I_DIM * H_DIM;           // [I, H] n-major
    const float* wuT = g_Y + Y_WU + (size_t)e * I_DIM * H_DIM;

    float dG[2][4][4] = {}, dU[2][4][4] = {};

    auto load_stage = [&](int kt, int b) {
        const int k0 = kt * BK;
        float* Ab = As + b * A_TB;
        float* Gb = Bg + b * B_TB;
        float* Ub = Bu + b * B_TB;
#pragma unroll
        for (int j = 0; j < 4; j++) {
            int idx = tid + 256 * j;              // 1024 float4 = 128 rows x 8
            int row = idx >> 3, c4 = idx & 7;
            cp16(Ab + row * STR + c4 * 4,
                 g_xt + (size_t)rtok[row] * H_DIM + k0 + c4 * 4);
        }
#pragma unroll
        for (int j = 0; j < 2; j++) {
            int idx = tid + 256 * j;              // 512 float4 = 64 rows x 8
            int row = idx >> 3, c4 = idx & 7;
            cp16(Gb + row * STR + c4 * 4,
                 wgT + (size_t)(n0 + row) * H_DIM + k0 + c4 * 4);
            cp16(Ub + row * STR + c4 * 4,
                 wuT + (size_t)(n0 + row) * H_DIM + k0 + c4 * 4);
        }
        cp_commit();
    };

    const int KT = H_DIM / BK;  // 32
    load_stage(0, 0);
    load_stage(1, 1);

    int bc = 0, bl = 2;   // compute buffer, load buffer
    for (int kt = 0; kt < KT; kt++) {
        if (kt + 1 < KT) cp_wait<1>(); else cp_wait<0>();
        __syncthreads();                       // single barrier per K-step
        if (kt + 2 < KT) load_stage(kt + 2, bl);

        const uint32_t As_t = sm_b + (uint32_t)bc * A_SB;
        const uint32_t Bg_t = sm_b + GU_OFF_BG + (uint32_t)bc * B_SB;
        const uint32_t Bu_t = sm_b + GU_OFF_BU + (uint32_t)bc * B_SB;

#pragma unroll
        for (int ks = 0; ks < 4; ks++) {
            uint32_t a[2][4];
            ldsm4(a[0], As_t + a_off + ks * 32);
            ldsm4(a[1], As_t + a_off + ROW16 + ks * 32);
            uint32_t f0[4], f1[4];
            ldsm4(f0, Bg_t + b_off + ks * 32);
            ldsm4(f1, Bg_t + b_off + ROW16 + ks * 32);
#pragma unroll
            for (int mi = 0; mi < 2; mi++) {
                mma_tf32(dG[mi][0], a[mi], &f0[0]);
                mma_tf32(dG[mi][1], a[mi], &f0[2]);
                mma_tf32(dG[mi][2], a[mi], &f1[0]);
                mma_tf32(dG[mi][3], a[mi], &f1[2]);
            }
            ldsm4(f0, Bu_t + b_off + ks * 32);
            ldsm4(f1, Bu_t + b_off + ROW16 + ks * 32);
#pragma unroll
            for (int mi = 0; mi < 2; mi++) {
                mma_tf32(dU[mi][0], a[mi], &f0[0]);
                mma_tf32(dU[mi][1], a[mi], &f0[2]);
                mma_tf32(dU[mi][2], a[mi], &f1[0]);
                mma_tf32(dU[mi][3], a[mi], &f1[2]);
            }
        }
        bc = (bc == 2) ? 0 : bc + 1;
        bl = (bl == 2) ? 0 : bl + 1;
    }

    // epilogue: hmid = tf32_round( silu(G) * U * combine_weight ), packed rows
#pragma unroll
    for (int mi = 0; mi < 2; mi++) {
#pragma unroll
        for (int ni = 0; ni < 4; ni++) {
            int rr = wm + mi * 16 + gid;
            int cc = wn + ni * 8 + tig * 2;
#pragma unroll
            for (int q = 0; q < 4; q++) {
                int r = rr + (q >> 1) * 8;
                int c = cc + (q & 1);
                if (m0 + r < n_e) {
                    float g = dG[mi][ni][q], u = dU[mi][ni][q];
                    float s = g / (1.f + expf(-g));
                    g_hmid[(size_t)(base + m0 + r) * I_DIM + n0 + c] =
                        tf32r(s * u * rw[r]);
                }
            }
        }
    }
}

// ---------------- launch 5: down grouped GEMM (3-stage, BK=32) ----------------------
__global__ void __launch_bounds__(256, 2) down_kernel()
{
    extern __shared__ char dsm[];
    const int e = blockIdx.z;
    const int n_e = g_counts[e];
    const int m0 = blockIdx.y * BM;
    if (m0 >= n_e) return;
    const int base = g_off[e];
    const int n0 = blockIdx.x * BN;

    float* As = (float*)dsm;
    float* Bs = (float*)(dsm + DN_OFF_B);

    const int tid = threadIdx.x;
    const int warp = tid >> 5, lane = tid & 31;
    const int gid = lane >> 2, tig = lane & 3;
    const int wm = (warp >> 1) * 32, wn = (warp & 1) * 32;

    const uint32_t a_off = (uint32_t)((wm + (lane & 7) + ((lane >> 3) & 1) * 8) * STR * 4
                                      + ((lane >> 4) & 1) * 16);
    const uint32_t b_off = (uint32_t)((wn + (lane & 7) + ((lane >> 4) & 1) * 8) * STR * 4
                                      + ((lane >> 3) & 1) * 16);
    const uint32_t sm_b = (uint32_t)__cvta_generic_to_shared(dsm);

    const float* Ain = g_hmid + (size_t)base * I_DIM;                   // packed rows
    const float* wdT = g_hmid + HM_WD + (size_t)e * H_DIM * I_DIM;      // [H, I] n-major

    float dD[2][4][4] = {};

    auto load_stage = [&](int kt, int b) {
        const int k0 = kt * BK;
        float* Ab = As + b * A_TB;
        float* Bb = Bs + b * B_TB;
#pragma unroll
        for (int j = 0; j < 4; j++) {
            int idx = tid + 256 * j;
            int row = idx >> 3, c4 = idx & 7;
            cp16(Ab + row * STR + c4 * 4,
                 Ain + (size_t)(m0 + row) * I_DIM + k0 + c4 * 4);
        }
#pragma unroll
        for (int j = 0; j < 2; j++) {
            int idx = tid + 256 * j;
            int row = idx >> 3, c4 = idx & 7;
            cp16(Bb + row * STR + c4 * 4,
                 wdT + (size_t)(n0 + row) * I_DIM + k0 + c4 * 4);
        }
        cp_commit();
    };

    const int KT = I_DIM / BK;  // 16
    load_stage(0, 0);
    load_stage(1, 1);

    int bc = 0, bl = 2;
    for (int kt = 0; kt < KT; kt++) {
        if (kt + 1 < KT) cp_wait<1>(); else cp_wait<0>();
        __syncthreads();
        if (kt + 2 < KT) load_stage(kt + 2, bl);

        const uint32_t As_t = sm_b + (uint32_t)bc * A_SB;
        const uint32_t Bs_t = sm_b + DN_OFF_B + (uint32_t)bc * B_SB;

#pragma unroll
        for (int ks = 0; ks < 4; ks++) {
            uint32_t a[2][4];
            ldsm4(a[0], As_t + a_off + ks * 32);
            ldsm4(a[1], As_t + a_off + ROW16 + ks * 32);
            uint32_t f0[4], f1[4];
            ldsm4(f0, Bs_t + b_off + ks * 32);
            ldsm4(f1, Bs_t + b_off + ROW16 + ks * 32);
#pragma unroll
            for (int mi = 0; mi < 2; mi++) {
                mma_tf32(dD[mi][0], a[mi], &f0[0]);
                mma_tf32(dD[mi][1], a[mi], &f0[2]);
                mma_tf32(dD[mi][2], a[mi], &f1[0]);
                mma_tf32(dD[mi][3], a[mi], &f1[2]);
            }
        }
        bc = (bc == 2) ? 0 : bc + 1;
        bl = (bl == 2) ? 0 : bl + 1;
    }

#pragma unroll
    for (int mi = 0; mi < 2; mi++) {
#pragma unroll
        for (int ni = 0; ni < 4; ni++) {
            int rr = wm + mi * 16 + gid;
            int cc = wn + ni * 8 + tig * 2;
#pragma unroll
            for (int q = 0; q < 4; q++) {
                int r = rr + (q >> 1) * 8;
                int c = cc + (q & 1);
                if (m0 + r < n_e)
                    g_Y[(size_t)(base + m0 + r) * H_DIM + n0 + c] = dD[mi][ni][q];
            }
        }
    }
}

// ---------------- launch 6: per-token combine ----------------
__global__ void __launch_bounds__(256) combine_kernel(float* __restrict__ out)
{
    const int t = blockIdx.x;
    __shared__ int slots[TOPK];
    if (threadIdx.x < TOPK) slots[threadIdx.x] = g_slot[t * TOPK + threadIdx.x];
    __syncthreads();

    int h4 = threadIdx.x;  // 256 float4 per token (H=1024)
    float4 acc = make_float4(0.f, 0.f, 0.f, 0.f);
#pragma unroll
    for (int k = 0; k < TOPK; k++) {
        const float4* y = (const float4*)(g_Y + (size_t)slots[k] * H_DIM);
        float4 v = y[h4];
        acc.x += v.x; acc.y += v.y; acc.z += v.z; acc.w += v.w;
    }
    ((float4*)out)[(size_t)t * (H_DIM / 4) + h4] = acc;
}

// ---------------- launch ----------------
extern "C" void kernel_launch(void* const* d_in, const int* in_sizes, int n_in,
                              void* d_out, int out_size)
{
    const float* x      = (const float*)d_in[0];  // [2,1024,1024]
    const float* gate_w = (const float*)d_in[1];  // [1024,16]
    const float* w_gate = (const float*)d_in[2];  // [16,1024,512]
    const float* w_up   = (const float*)d_in[3];  // [16,1024,512]
    const float* w_down = (const float*)d_in[4];  // [16,512,1024]
    float* out = (float*)d_out;

    float* logits = nullptr;
    if (out_size >= T_TOK * H_DIM + T_TOK * N_EXP)
        logits = out + (size_t)T_TOK * H_DIM;

    cudaFuncSetAttribute(gu_kernel,   cudaFuncAttributeMaxDynamicSharedMemorySize, GU_SMEM);
    cudaFuncSetAttribute(down_kernel, cudaFuncAttributeMaxDynamicSharedMemorySize, DN_SMEM);

    prep_kernel<<<dim3(32, 32, 49), dim3(32, 8)>>>(x, w_gate, w_up, w_down);  // launch 1
    router_kernel<<<T_TOK / 8, 256>>>(x, gate_w, logits);                     // launch 2
    scatter_kernel<<<TROWS / 256, 256>>>();                                   // launch 3
    gu_kernel<<<dim3(I_DIM / BN, 16, N_EXP), 256, GU_SMEM>>>();               // launch 4 (ncu)
    down_kernel<<<dim3(H_DIM / BN, 16, N_EXP), 256, DN_SMEM>>>();             // launch 5
    combine_kernel<<<T_TOK, 256>>>(out);                                      // launch 6
}